// round 15
// baseline (speedup 1.0000x reference)
#include <cuda_runtime.h>
#include <cstdint>

#define N_NODES 50000
#define D 128
#define DOUT 64
#define E_EDGES 800000

#define SCAN_BLK 2048
#define SCAN_GRID 25   // 25 blocks, co-resident by construction

// prep blocks (256 threads each): 32 (Wc, 2 k-pairs each) + 1 (bias) + 16 (W2) = 49
#define PREP_BLOCKS 49
#define HIST_BLOCKS ((E_EDGES / 4 + 255) / 256)    // 782
#define PH_BLOCKS (PREP_BLOCKS + HIST_BLOCKS)

// ---------------- device globals (zero-initialized at module load) --------
__device__ __align__(16) float g_agg1[N_NODES * D];
__device__ __align__(16) float g_h2[N_NODES * DOUT];
__device__ __align__(16) float g_bc[D];
// [0..N) = histogram (re-zeroed by scan each run); [N]=arrive, [N+1]=done, [N+4]=flag
__device__ int g_rowcnt[N_NODES + 8];
__device__ int g_rowptr[N_NODES + 1];
__device__ __align__(16) int g_rank[E_EDGES];
__device__ int g_csr_src[E_EDGES];
__device__ int g_blocksum[SCAN_GRID];
// packed bf16x2 weight images, transposed: [out_col][k_pair]
__device__ __align__(16) uint32_t g_WcP_h[D * (D / 2)];
__device__ __align__(16) uint32_t g_WcP_l[D * (D / 2)];
__device__ __align__(16) uint32_t g_W2P_h[DOUT * (D / 2)];
__device__ __align__(16) uint32_t g_W2P_l[DOUT * (D / 2)];

// ---------------- bf16 helpers ----------------
// pack: e0 -> low half (even k), e1 -> high half (odd k)
__device__ __forceinline__ uint32_t pack_bf16x2(float e0, float e1) {
    uint32_t r;
    asm("cvt.rn.bf16x2.f32 %0, %1, %2;" : "=r"(r) : "f"(e1), "f"(e0));
    return r;
}

// split a pair of floats into bf16 hi word + bf16 lo (residual) word
__device__ __forceinline__ void split_pack(float e0, float e1,
                                           uint32_t& hw, uint32_t& lw) {
    hw = pack_bf16x2(e0, e1);
    float h0 = __uint_as_float(hw << 16);
    float h1 = __uint_as_float(hw & 0xffff0000u);
    lw = pack_bf16x2(e0 - h0, e1 - h1);
}

__device__ __forceinline__ void mma_bf16(float* d, const uint32_t* a,
                                         uint32_t b0, uint32_t b1) {
    asm volatile(
        "mma.sync.aligned.m16n8k16.row.col.f32.bf16.bf16.f32 "
        "{%0,%1,%2,%3}, {%4,%5,%6,%7}, {%8,%9}, {%0,%1,%2,%3};"
        : "+f"(d[0]), "+f"(d[1]), "+f"(d[2]), "+f"(d[3])
        : "r"(a[0]), "r"(a[1]), "r"(a[2]), "r"(a[3]), "r"(b0), "r"(b1));
}

// ---------------------------------------------------------------------------
// Merged prep + hist (256 threads/block).
// ---------------------------------------------------------------------------
__global__ void prephist_kernel(const int* __restrict__ dst,
                                const float* __restrict__ W_pre,
                                const float* __restrict__ b_pre,
                                const float* __restrict__ W1,
                                const float* __restrict__ b1,
                                const float* __restrict__ W2) {
    int bid = blockIdx.x;
    int tid = threadIdx.x;
    if (bid < 32) {
        int kp = bid * 2 + (tid >> 7);   // 0..63
        int c = tid & 127;
        float acc0 = 0.f, acc1 = 0.f;
#pragma unroll 8
        for (int k = 0; k < D; k++) {
            float w1 = W1[k * D + c];
            acc0 += W_pre[(2 * kp) * D + k] * w1;
            acc1 += W_pre[(2 * kp + 1) * D + k] * w1;
        }
        uint32_t hw, lw;
        split_pack(acc0, acc1, hw, lw);
        g_WcP_h[c * (D / 2) + kp] = hw;
        g_WcP_l[c * (D / 2) + kp] = lw;
    } else if (bid == 32) {
        if (tid < D) {
            int c = tid;
            float acc = b1[c];
#pragma unroll 8
            for (int k = 0; k < D; k++) acc += b_pre[k] * W1[k * D + c];
            g_bc[c] = acc;
        }
    } else if (bid < PREP_BLOCKS) {
        int id = (bid - 33) * 256 + tid;   // 0..4095
        if (id < DOUT * (D / 2)) {
            int n = id >> 6;
            int kp = id & 63;
            float w0 = W2[(2 * kp) * DOUT + n];
            float w1 = W2[(2 * kp + 1) * DOUT + n];
            uint32_t hw, lw;
            split_pack(w0, w1, hw, lw);
            g_W2P_h[n * (D / 2) + kp] = hw;
            g_W2P_l[n * (D / 2) + kp] = lw;
        }
    } else {
        int e4 = ((bid - PREP_BLOCKS) * 256 + tid) * 4;
        if (e4 < E_EDGES) {
            int4 d = *reinterpret_cast<const int4*>(dst + e4);
            int4 rk;
            rk.x = atomicAdd(&g_rowcnt[d.x], 1);
            rk.y = atomicAdd(&g_rowcnt[d.y], 1);
            rk.z = atomicAdd(&g_rowcnt[d.z], 1);
            rk.w = atomicAdd(&g_rowcnt[d.w], 1);
            *reinterpret_cast<int4*>(g_rank + e4) = rk;
        }
    }
}

// ---------------------------------------------------------------------------
// Scan: exclusive scan of rowcnt -> rowptr; self-resetting for graph replay
// ---------------------------------------------------------------------------
__global__ void scan_kernel() {
    __shared__ int sh[9];
    int tid = threadIdx.x;
    int bid = blockIdx.x;
    int lane = tid & 31, warp = tid >> 5;
    int base = bid * SCAN_BLK + tid * 8;

    int v[8], s = 0;
#pragma unroll
    for (int j = 0; j < 8; j++) {
        int i = base + j;
        v[j] = (i < N_NODES) ? g_rowcnt[i] : 0;
        if (i < N_NODES) g_rowcnt[i] = 0;
        s += v[j];
    }
    int ps = s;
#pragma unroll
    for (int off = 1; off < 32; off <<= 1) {
        int n = __shfl_up_sync(0xffffffffu, ps, off);
        if (lane >= off) ps += n;
    }
    if (lane == 31) sh[warp] = ps;
    __syncthreads();
    if (warp == 0 && lane < 8) {
        int ws = sh[lane];
#pragma unroll
        for (int off = 1; off < 8; off <<= 1) {
            int n = __shfl_up_sync(0x000000ffu, ws, off);
            if (lane >= off) ws += n;
        }
        sh[lane] = ws;
    }
    __syncthreads();
    int woff = (warp == 0) ? 0 : sh[warp - 1];
    int excl = ps - s + woff;
    int run = excl;
    int local[8];
#pragma unroll
    for (int j = 0; j < 8; j++) {
        local[j] = run;
        run += v[j];
    }
    if (tid == 255) g_blocksum[bid] = run;

    __syncthreads();
    if (tid == 0) {
        int t = atomicAdd(&g_rowcnt[N_NODES], 1);
        if (t == SCAN_GRID - 1) {
            __threadfence();
            ((volatile int*)g_rowcnt)[N_NODES + 4] = 1;
        } else {
            while (((volatile int*)g_rowcnt)[N_NODES + 4] == 0) {}
            __threadfence();
        }
    }
    __syncthreads();

    if (tid < 32) {
        int l2 = tid;
        int bv = (l2 < SCAN_GRID) ? g_blocksum[l2] : 0;
        int bps = bv;
#pragma unroll
        for (int off = 1; off < 32; off <<= 1) {
            int n = __shfl_up_sync(0xffffffffu, bps, off);
            if (l2 >= off) bps += n;
        }
        if (l2 == bid) sh[8] = bps - bv;
        if (bid == SCAN_GRID - 1 && l2 == SCAN_GRID - 1)
            g_rowptr[N_NODES] = bps;
    }
    __syncthreads();
    int off = sh[8];
#pragma unroll
    for (int j = 0; j < 8; j++) {
        int i = base + j;
        if (i < N_NODES) g_rowptr[i] = local[j] + off;
    }

    __syncthreads();
    if (tid == 0) {
        int t = atomicAdd(&g_rowcnt[N_NODES + 1], 1);
        if (t == SCAN_GRID - 1) {
            g_rowcnt[N_NODES] = 0;
            g_rowcnt[N_NODES + 1] = 0;
            ((volatile int*)g_rowcnt)[N_NODES + 4] = 0;
        }
    }
}

// fill: pos = rowptr[dst] + rank; 8 edges per thread for MLP
__global__ void fill_kernel(const int* __restrict__ src,
                            const int* __restrict__ dst) {
    int e8 = (blockIdx.x * blockDim.x + threadIdx.x) * 8;
    if (e8 < E_EDGES) {
        int4 s0 = *reinterpret_cast<const int4*>(src + e8);
        int4 s1 = *reinterpret_cast<const int4*>(src + e8 + 4);
        int4 d0 = *reinterpret_cast<const int4*>(dst + e8);
        int4 d1 = *reinterpret_cast<const int4*>(dst + e8 + 4);
        int4 r0 = *reinterpret_cast<const int4*>(g_rank + e8);
        int4 r1 = *reinterpret_cast<const int4*>(g_rank + e8 + 4);
        int p0 = __ldg(&g_rowptr[d0.x]);
        int p1 = __ldg(&g_rowptr[d0.y]);
        int p2 = __ldg(&g_rowptr[d0.z]);
        int p3 = __ldg(&g_rowptr[d0.w]);
        int p4 = __ldg(&g_rowptr[d1.x]);
        int p5 = __ldg(&g_rowptr[d1.y]);
        int p6 = __ldg(&g_rowptr[d1.z]);
        int p7 = __ldg(&g_rowptr[d1.w]);
        g_csr_src[p0 + r0.x] = s0.x;
        g_csr_src[p1 + r0.y] = s0.y;
        g_csr_src[p2 + r0.z] = s0.z;
        g_csr_src[p3 + r0.w] = s0.w;
        g_csr_src[p4 + r1.x] = s1.x;
        g_csr_src[p5 + r1.y] = s1.y;
        g_csr_src[p6 + r1.z] = s1.z;
        g_csr_src[p7 + r1.w] = s1.w;
    }
}

// ---------------------------------------------------------------------------
// Gather layer 1 (fp32, 128 dims, warp per node) — 4x unrolled
// ---------------------------------------------------------------------------
__global__ void gather1_kernel(const float* __restrict__ x) {
    int node = (blockIdx.x * blockDim.x + threadIdx.x) >> 5;
    int lane = threadIdx.x & 31;
    if (node >= N_NODES) return;
    int beg = g_rowptr[node];
    int end = g_rowptr[node + 1];

    float4 acc = *reinterpret_cast<const float4*>(x + (size_t)node * D + lane * 4);

    for (int base = beg; base < end; base += 32) {
        int idx = 0;
        if (base + lane < end) idx = __ldg(&g_csr_src[base + lane]);
        int m = end - base; if (m > 32) m = 32;
        int j = 0;
        for (; j + 4 <= m; j += 4) {
            int s0 = __shfl_sync(0xffffffffu, idx, j);
            int s1 = __shfl_sync(0xffffffffu, idx, j + 1);
            int s2 = __shfl_sync(0xffffffffu, idx, j + 2);
            int s3 = __shfl_sync(0xffffffffu, idx, j + 3);
            float4 v0 = *reinterpret_cast<const float4*>(x + (size_t)s0 * D + lane * 4);
            float4 v1 = *reinterpret_cast<const float4*>(x + (size_t)s1 * D + lane * 4);
            float4 v2 = *reinterpret_cast<const float4*>(x + (size_t)s2 * D + lane * 4);
            float4 v3 = *reinterpret_cast<const float4*>(x + (size_t)s3 * D + lane * 4);
            acc.x += (v0.x + v1.x) + (v2.x + v3.x);
            acc.y += (v0.y + v1.y) + (v2.y + v3.y);
            acc.z += (v0.z + v1.z) + (v2.z + v3.z);
            acc.w += (v0.w + v1.w) + (v2.w + v3.w);
        }
        for (; j < m; j++) {
            int s = __shfl_sync(0xffffffffu, idx, j);
            float4 v = *reinterpret_cast<const float4*>(x + (size_t)s * D + lane * 4);
            acc.x += v.x; acc.y += v.y; acc.z += v.z; acc.w += v.w;
        }
    }
    float inv = 1.0f / (float)(end - beg + 1);
    acc.x *= inv; acc.y *= inv; acc.z *= inv; acc.w *= inv;
    *reinterpret_cast<float4*>(g_agg1 + (size_t)node * D + lane * 4) = acc;
}

// ---------------------------------------------------------------------------
// Fused two-layer GEMM via mma.sync bf16 (2-way split, 3 products).
// 256 threads, 64-row tile, 2 blocks/SM. Packed bf16x2 tiles, stride 68 words.
// smem: bias 512B + A hi/lo 2*64*68*4 = 34.8KB + W hi/lo 2*128*68*4 = 69.6KB
// ---------------------------------------------------------------------------
#define KW 64            // k-pairs per row
#define KWS 68           // padded word stride
#define AROWS 64
#define ATILE_W (AROWS * KWS)
#define WTILE_W (128 * KWS)
#define FG_SMEM ((128 + 2 * ATILE_W + 2 * WTILE_W) * 4)

__global__ void __launch_bounds__(256, 2) fusedgemm_kernel() {
    extern __shared__ uint32_t smu[];
    float* bias    = (float*)smu;          // 128 floats
    uint32_t* sAh  = smu + 128;
    uint32_t* sAl  = sAh + ATILE_W;
    uint32_t* sWh  = sAl + ATILE_W;
    uint32_t* sWl  = sWh + WTILE_W;

    int tid = threadIdx.x;
    int w = tid >> 5, lane = tid & 31;
    int g = lane >> 2, qi = lane & 3;
    int row0 = blockIdx.x * AROWS;

    if (tid < D) bias[tid] = g_bc[tid];
    // A tile: load fp32, split+pack into sAh/sAl (64 rows)
    for (int i = tid; i < AROWS * 32; i += 256) {
        int r = i >> 5, c4 = (i & 31) << 2;
        float4 v = make_float4(0.f, 0.f, 0.f, 0.f);
        int row = row0 + r;
        if (row < N_NODES) v = *reinterpret_cast<const float4*>(g_agg1 + (size_t)row * D + c4);
        uint32_t hw0, lw0, hw1, lw1;
        split_pack(v.x, v.y, hw0, lw0);
        split_pack(v.z, v.w, hw1, lw1);
        int o = r * KWS + (c4 >> 1);
        sAh[o] = hw0; sAh[o + 1] = hw1;
        sAl[o] = lw0; sAl[o + 1] = lw1;
    }
    // Wc packed images -> smem (stride 64 -> 68)
    for (int i = tid; i < 128 * 32; i += 256) {  // uint2 units
        int r = i >> 5, kw2 = (i & 31) << 1;
        uint2 h = *reinterpret_cast<const uint2*>(&g_WcP_h[r * KW + kw2]);
        uint2 l = *reinterpret_cast<const uint2*>(&g_WcP_l[r * KW + kw2]);
        *reinterpret_cast<uint2*>(&sWh[r * KWS + kw2]) = h;
        *reinterpret_cast<uint2*>(&sWl[r * KWS + kw2]) = l;
    }
    __syncthreads();

    // ---- layer 1: 64x128 output; 8 warps: 2 row-bands x 4 col-bands (32x32) ----
    int rw0 = (w >> 2) * 32;
    int cw0 = (w & 3) * 32;
    float acc[2][4][4];
#pragma unroll
    for (int mt = 0; mt < 2; mt++)
#pragma unroll
        for (int nt = 0; nt < 4; nt++)
#pragma unroll
            for (int j = 0; j < 4; j++) acc[mt][nt][j] = 0.f;

#pragma unroll
    for (int ks = 0; ks < 8; ks++) {
        int kw0 = ks * 8;
        uint32_t ah[2][4], al[2][4];
#pragma unroll
        for (int mt = 0; mt < 2; mt++) {
            int rb = rw0 + mt * 16;
            ah[mt][0] = sAh[(rb + g) * KWS + kw0 + qi];
            ah[mt][1] = sAh[(rb + g + 8) * KWS + kw0 + qi];
            ah[mt][2] = sAh[(rb + g) * KWS + kw0 + qi + 4];
            ah[mt][3] = sAh[(rb + g + 8) * KWS + kw0 + qi + 4];
            al[mt][0] = sAl[(rb + g) * KWS + kw0 + qi];
            al[mt][1] = sAl[(rb + g + 8) * KWS + kw0 + qi];
            al[mt][2] = sAl[(rb + g) * KWS + kw0 + qi + 4];
            al[mt][3] = sAl[(rb + g + 8) * KWS + kw0 + qi + 4];
        }
#pragma unroll
        for (int nt = 0; nt < 4; nt++) {
            int nb = cw0 + nt * 8 + g;
            uint32_t bh0 = sWh[nb * KWS + kw0 + qi];
            uint32_t bh1 = sWh[nb * KWS + kw0 + qi + 4];
            uint32_t bl0 = sWl[nb * KWS + kw0 + qi];
            uint32_t bl1 = sWl[nb * KWS + kw0 + qi + 4];
#pragma unroll
            for (int mt = 0; mt < 2; mt++) {
                mma_bf16(acc[mt][nt], ah[mt], bh0, bh1);
                mma_bf16(acc[mt][nt], al[mt], bh0, bh1);
                mma_bf16(acc[mt][nt], ah[mt], bl0, bl1);
            }
        }
    }
    __syncthreads();

    // ---- epilogue 1: bias + relu, split-pack h1 back into sAh/sAl ----
#pragma unroll
    for (int mt = 0; mt < 2; mt++) {
        int rb = rw0 + mt * 16;
#pragma unroll
        for (int nt = 0; nt < 4; nt++) {
            int c0 = cw0 + nt * 8 + qi * 2;
            float b0 = bias[c0], b1 = bias[c0 + 1];
            int ow = (c0 >> 1);
            {
                float f0 = fmaxf(acc[mt][nt][0] + b0, 0.f);
                float f1 = fmaxf(acc[mt][nt][1] + b1, 0.f);
                uint32_t hw, lw;
                split_pack(f0, f1, hw, lw);
                sAh[(rb + g) * KWS + ow] = hw;
                sAl[(rb + g) * KWS + ow] = lw;
            }
            {
                float f0 = fmaxf(acc[mt][nt][2] + b0, 0.f);
                float f1 = fmaxf(acc[mt][nt][3] + b1, 0.f);
                uint32_t hw, lw;
                split_pack(f0, f1, hw, lw);
                sAh[(rb + g + 8) * KWS + ow] = hw;
                sAl[(rb + g + 8) * KWS + ow] = lw;
            }
        }
    }
    __syncthreads();

    // ---- W2 packed images (alias sWh/sWl region) ----
    for (int i = tid; i < DOUT * 32; i += 256) {  // uint2 units
        int r = i >> 5, kw2 = (i & 31) << 1;
        uint2 h = *reinterpret_cast<const uint2*>(&g_W2P_h[r * KW + kw2]);
        uint2 l = *reinterpret_cast<const uint2*>(&g_W2P_l[r * KW + kw2]);
        *reinterpret_cast<uint2*>(&sWh[r * KWS + kw2]) = h;
        *reinterpret_cast<uint2*>(&sWl[r * KWS + kw2]) = l;
    }
    __syncthreads();

    // ---- layer 2: 64x64 output; warp tile 32 rows x 16 cols ----
    int cw2 = (w & 3) * 16;
    float acc2[2][2][4];
#pragma unroll
    for (int mt = 0; mt < 2; mt++)
#pragma unroll
        for (int nt = 0; nt < 2; nt++)
#pragma unroll
            for (int j = 0; j < 4; j++) acc2[mt][nt][j] = 0.f;

#pragma unroll
    for (int ks = 0; ks < 8; ks++) {
        int kw0 = ks * 8;
        uint32_t ah[2][4], al[2][4];
#pragma unroll
        for (int mt = 0; mt < 2; mt++) {
            int rb = rw0 + mt * 16;
            ah[mt][0] = sAh[(rb + g) * KWS + kw0 + qi];
            ah[mt][1] = sAh[(rb + g + 8) * KWS + kw0 + qi];
            ah[mt][2] = sAh[(rb + g) * KWS + kw0 + qi + 4];
            ah[mt][3] = sAh[(rb + g + 8) * KWS + kw0 + qi + 4];
            al[mt][0] = sAl[(rb + g) * KWS + kw0 + qi];
            al[mt][1] = sAl[(rb + g + 8) * KWS + kw0 + qi];
            al[mt][2] = sAl[(rb + g) * KWS + kw0 + qi + 4];
            al[mt][3] = sAl[(rb + g + 8) * KWS + kw0 + qi + 4];
        }
#pragma unroll
        for (int nt = 0; nt < 2; nt++) {
            int nb = cw2 + nt * 8 + g;
            uint32_t bh0 = sWh[nb * KWS + kw0 + qi];
            uint32_t bh1 = sWh[nb * KWS + kw0 + qi + 4];
            uint32_t bl0 = sWl[nb * KWS + kw0 + qi];
            uint32_t bl1 = sWl[nb * KWS + kw0 + qi + 4];
#pragma unroll
            for (int mt = 0; mt < 2; mt++) {
                mma_bf16(acc2[mt][nt], ah[mt], bh0, bh1);
                mma_bf16(acc2[mt][nt], al[mt], bh0, bh1);
                mma_bf16(acc2[mt][nt], ah[mt], bl0, bl1);
            }
        }
    }
    __syncthreads();

    // ---- epilogue 2: stage h2 fp32 in smem (stride 66), coalesced store ----
    float* h2s = (float*)sAh;   // 64*66*4 = 16.9KB fits in sAh tile
#pragma unroll
    for (int mt = 0; mt < 2; mt++) {
        int rb = rw0 + mt * 16;
#pragma unroll
        for (int nt = 0; nt < 2; nt++) {
            int c0 = cw2 + nt * 8 + qi * 2;
            h2s[(rb + g) * 66 + c0]         = acc2[mt][nt][0];
            h2s[(rb + g) * 66 + c0 + 1]     = acc2[mt][nt][1];
            h2s[(rb + g + 8) * 66 + c0]     = acc2[mt][nt][2];
            h2s[(rb + g + 8) * 66 + c0 + 1] = acc2[mt][nt][3];
        }
    }
    __syncthreads();
    for (int i = tid; i < AROWS * 32; i += 256) {
        int r = i >> 5, c2 = (i & 31) << 1;
        int row = row0 + r;
        if (row < N_NODES) {
            float2 v = *reinterpret_cast<const float2*>(&h2s[r * 66 + c2]);
            *reinterpret_cast<float2*>(&g_h2[(size_t)row * DOUT + c2]) = v;
        }
    }
}

// ---------------------------------------------------------------------------
// Gather layer 2 + bias + L2 normalize: HALF-WARP per node, float4 lanes
// ---------------------------------------------------------------------------
__global__ void gather2_kernel(const float* __restrict__ b2,
                               float* __restrict__ out) {
    int gw = (blockIdx.x * blockDim.x + threadIdx.x) >> 5;
    int lane = threadIdx.x & 31;
    int half = lane >> 4, l = lane & 15;
    int node = gw * 2 + half;
    if (node >= N_NODES) return;
    unsigned hmask = 0xFFFFu << (half * 16);
    int sbase = half * 16;

    int beg = g_rowptr[node];
    int end = g_rowptr[node + 1];

    float4 acc = *reinterpret_cast<const float4*>(g_h2 + (size_t)node * DOUT + l * 4);

    for (int base = beg; base < end; base += 16) {
        int idx = 0;
        if (base + l < end) idx = __ldg(&g_csr_src[base + l]);
        int m = end - base; if (m > 16) m = 16;
        int j = 0;
        for (; j + 4 <= m; j += 4) {
            int s0 = __shfl_sync(hmask, idx, sbase + j);
            int s1 = __shfl_sync(hmask, idx, sbase + j + 1);
            int s2 = __shfl_sync(hmask, idx, sbase + j + 2);
            int s3 = __shfl_sync(hmask, idx, sbase + j + 3);
            float4 v0 = *reinterpret_cast<const float4*>(g_h2 + (size_t)s0 * DOUT + l * 4);
            float4 v1 = *reinterpret_cast<const float4*>(g_h2 + (size_t)s1 * DOUT + l * 4);
            float4 v2 = *reinterpret_cast<const float4*>(g_h2 + (size_t)s2 * DOUT + l * 4);
            float4 v3 = *reinterpret_cast<const float4*>(g_h2 + (size_t)s3 * DOUT + l * 4);
            acc.x += (v0.x + v1.x) + (v2.x + v3.x);
            acc.y += (v0.y + v1.y) + (v2.y + v3.y);
            acc.z += (v0.z + v1.z) + (v2.z + v3.z);
            acc.w += (v0.w + v1.w) + (v2.w + v3.w);
        }
        for (; j < m; j++) {
            int s = __shfl_sync(hmask, idx, sbase + j);
            float4 v = *reinterpret_cast<const float4*>(g_h2 + (size_t)s * DOUT + l * 4);
            acc.x += v.x; acc.y += v.y; acc.z += v.z; acc.w += v.w;
        }
    }
    float inv = 1.0f / (float)(end - beg + 1);
    float4 b = *reinterpret_cast<const float4*>(b2 + l * 4);
    float a0 = acc.x * inv + b.x;
    float a1 = acc.y * inv + b.y;
    float a2 = acc.z * inv + b.z;
    float a3 = acc.w * inv + b.w;
    float ss = a0 * a0 + a1 * a1 + a2 * a2 + a3 * a3;
#pragma unroll
    for (int o = 8; o; o >>= 1) ss += __shfl_xor_sync(hmask, ss, o);
    float s = 1.0f / fmaxf(sqrtf(ss), 1e-12f);
    float4 o4 = make_float4(a0 * s, a1 * s, a2 * s, a3 * s);
    *reinterpret_cast<float4*>(&out[(size_t)node * DOUT + l * 4]) = o4;
}

// ---------------------------------------------------------------------------
extern "C" void kernel_launch(void* const* d_in, const int* in_sizes, int n_in,
                              void* d_out, int out_size) {
    const float* x     = (const float*)d_in[0];
    const int*   ei    = (const int*)d_in[1];
    const float* W_pre = (const float*)d_in[2];
    const float* b_pre = (const float*)d_in[3];
    const float* W1    = (const float*)d_in[4];
    const float* b1    = (const float*)d_in[5];
    const float* W2    = (const float*)d_in[6];
    const float* b2    = (const float*)d_in[7];
    float* out = (float*)d_out;

    const int* src = ei;
    const int* dst = ei + E_EDGES;

    static bool attr_set = false;
    if (!attr_set) {
        cudaFuncSetAttribute(fusedgemm_kernel,
                             cudaFuncAttributeMaxDynamicSharedMemorySize, FG_SMEM);
        attr_set = true;
    }

    prephist_kernel<<<PH_BLOCKS, 256>>>(dst, W_pre, b_pre, W1, b1, W2);
    scan_kernel<<<SCAN_GRID, 256>>>();
    fill_kernel<<<(E_EDGES / 8 + 255) / 256, 256>>>(src, dst);
    gather1_kernel<<<(N_NODES * 32 + 255) / 256, 256>>>(x);
    fusedgemm_kernel<<<(N_NODES + AROWS - 1) / AROWS, 256, FG_SMEM>>>();
    gather2_kernel<<<((N_NODES + 1) / 2 * 32 + 255) / 256, 256>>>(b2, out);
}

// round 16
// speedup vs baseline: 1.0499x; 1.0499x over previous
#include <cuda_runtime.h>
#include <cstdint>

#define N_NODES 50000
#define D 128
#define DOUT 64
#define E_EDGES 800000

#define SCAN_BLK 2048
#define SCAN_GRID 25   // 25 blocks, co-resident by construction

// prep blocks (256 threads each): 32 (Wc, 2 k-pairs each) + 1 (bias) + 16 (W2) = 49
#define PREP_BLOCKS 49
#define HIST_BLOCKS ((E_EDGES / 4 + 255) / 256)    // 782
#define PH_BLOCKS (PREP_BLOCKS + HIST_BLOCKS)

// ---------------- device globals (zero-initialized at module load) --------
__device__ __align__(16) float g_agg1[N_NODES * D];
__device__ __align__(16) float g_h2[N_NODES * DOUT];
__device__ __align__(16) float g_bc[D];
// [0..N) = histogram (re-zeroed by scan each run); [N]=arrive, [N+1]=done, [N+4]=flag
__device__ int g_rowcnt[N_NODES + 8];
__device__ int g_rowptr[N_NODES + 1];
__device__ __align__(16) int g_rank[E_EDGES];
__device__ int g_csr_src[E_EDGES];
__device__ int g_blocksum[SCAN_GRID];
// packed bf16x2 weight images, transposed: [out_col][k_pair]
__device__ __align__(16) uint32_t g_WcP_h[D * (D / 2)];
__device__ __align__(16) uint32_t g_WcP_l[D * (D / 2)];
__device__ __align__(16) uint32_t g_W2P_h[DOUT * (D / 2)];
__device__ __align__(16) uint32_t g_W2P_l[DOUT * (D / 2)];

// ---------------- bf16 helpers ----------------
__device__ __forceinline__ uint32_t pack_bf16x2(float e0, float e1) {
    uint32_t r;
    asm("cvt.rn.bf16x2.f32 %0, %1, %2;" : "=r"(r) : "f"(e1), "f"(e0));
    return r;
}

__device__ __forceinline__ void split_pack(float e0, float e1,
                                           uint32_t& hw, uint32_t& lw) {
    hw = pack_bf16x2(e0, e1);
    float h0 = __uint_as_float(hw << 16);
    float h1 = __uint_as_float(hw & 0xffff0000u);
    lw = pack_bf16x2(e0 - h0, e1 - h1);
}

__device__ __forceinline__ void mma_bf16(float* d, const uint32_t* a,
                                         uint32_t b0, uint32_t b1) {
    asm volatile(
        "mma.sync.aligned.m16n8k16.row.col.f32.bf16.bf16.f32 "
        "{%0,%1,%2,%3}, {%4,%5,%6,%7}, {%8,%9}, {%0,%1,%2,%3};"
        : "+f"(d[0]), "+f"(d[1]), "+f"(d[2]), "+f"(d[3])
        : "r"(a[0]), "r"(a[1]), "r"(a[2]), "r"(a[3]), "r"(b0), "r"(b1));
}

// ---------------------------------------------------------------------------
// Merged prep + hist (256 threads/block).
// ---------------------------------------------------------------------------
__global__ void prephist_kernel(const int* __restrict__ dst,
                                const float* __restrict__ W_pre,
                                const float* __restrict__ b_pre,
                                const float* __restrict__ W1,
                                const float* __restrict__ b1,
                                const float* __restrict__ W2) {
    int bid = blockIdx.x;
    int tid = threadIdx.x;
    if (bid < 32) {
        int kp = bid * 2 + (tid >> 7);   // 0..63
        int c = tid & 127;
        float acc0 = 0.f, acc1 = 0.f;
#pragma unroll 8
        for (int k = 0; k < D; k++) {
            float w1 = W1[k * D + c];
            acc0 += W_pre[(2 * kp) * D + k] * w1;
            acc1 += W_pre[(2 * kp + 1) * D + k] * w1;
        }
        uint32_t hw, lw;
        split_pack(acc0, acc1, hw, lw);
        g_WcP_h[c * (D / 2) + kp] = hw;
        g_WcP_l[c * (D / 2) + kp] = lw;
    } else if (bid == 32) {
        if (tid < D) {
            int c = tid;
            float acc = b1[c];
#pragma unroll 8
            for (int k = 0; k < D; k++) acc += b_pre[k] * W1[k * D + c];
            g_bc[c] = acc;
        }
    } else if (bid < PREP_BLOCKS) {
        int id = (bid - 33) * 256 + tid;   // 0..4095
        if (id < DOUT * (D / 2)) {
            int n = id >> 6;
            int kp = id & 63;
            float w0 = W2[(2 * kp) * DOUT + n];
            float w1 = W2[(2 * kp + 1) * DOUT + n];
            uint32_t hw, lw;
            split_pack(w0, w1, hw, lw);
            g_W2P_h[n * (D / 2) + kp] = hw;
            g_W2P_l[n * (D / 2) + kp] = lw;
        }
    } else {
        int e4 = ((bid - PREP_BLOCKS) * 256 + tid) * 4;
        if (e4 < E_EDGES) {
            int4 d = *reinterpret_cast<const int4*>(dst + e4);
            int4 rk;
            rk.x = atomicAdd(&g_rowcnt[d.x], 1);
            rk.y = atomicAdd(&g_rowcnt[d.y], 1);
            rk.z = atomicAdd(&g_rowcnt[d.z], 1);
            rk.w = atomicAdd(&g_rowcnt[d.w], 1);
            *reinterpret_cast<int4*>(g_rank + e4) = rk;
        }
    }
}

// ---------------------------------------------------------------------------
// Scan: exclusive scan of rowcnt -> rowptr; self-resetting for graph replay
// ---------------------------------------------------------------------------
__global__ void scan_kernel() {
    __shared__ int sh[9];
    int tid = threadIdx.x;
    int bid = blockIdx.x;
    int lane = tid & 31, warp = tid >> 5;
    int base = bid * SCAN_BLK + tid * 8;

    int v[8], s = 0;
#pragma unroll
    for (int j = 0; j < 8; j++) {
        int i = base + j;
        v[j] = (i < N_NODES) ? g_rowcnt[i] : 0;
        if (i < N_NODES) g_rowcnt[i] = 0;
        s += v[j];
    }
    int ps = s;
#pragma unroll
    for (int off = 1; off < 32; off <<= 1) {
        int n = __shfl_up_sync(0xffffffffu, ps, off);
        if (lane >= off) ps += n;
    }
    if (lane == 31) sh[warp] = ps;
    __syncthreads();
    if (warp == 0 && lane < 8) {
        int ws = sh[lane];
#pragma unroll
        for (int off = 1; off < 8; off <<= 1) {
            int n = __shfl_up_sync(0x000000ffu, ws, off);
            if (lane >= off) ws += n;
        }
        sh[lane] = ws;
    }
    __syncthreads();
    int woff = (warp == 0) ? 0 : sh[warp - 1];
    int excl = ps - s + woff;
    int run = excl;
    int local[8];
#pragma unroll
    for (int j = 0; j < 8; j++) {
        local[j] = run;
        run += v[j];
    }
    if (tid == 255) g_blocksum[bid] = run;

    __syncthreads();
    if (tid == 0) {
        int t = atomicAdd(&g_rowcnt[N_NODES], 1);
        if (t == SCAN_GRID - 1) {
            __threadfence();
            ((volatile int*)g_rowcnt)[N_NODES + 4] = 1;
        } else {
            while (((volatile int*)g_rowcnt)[N_NODES + 4] == 0) {}
            __threadfence();
        }
    }
    __syncthreads();

    if (tid < 32) {
        int l2 = tid;
        int bv = (l2 < SCAN_GRID) ? g_blocksum[l2] : 0;
        int bps = bv;
#pragma unroll
        for (int off = 1; off < 32; off <<= 1) {
            int n = __shfl_up_sync(0xffffffffu, bps, off);
            if (l2 >= off) bps += n;
        }
        if (l2 == bid) sh[8] = bps - bv;
        if (bid == SCAN_GRID - 1 && l2 == SCAN_GRID - 1)
            g_rowptr[N_NODES] = bps;
    }
    __syncthreads();
    int off = sh[8];
#pragma unroll
    for (int j = 0; j < 8; j++) {
        int i = base + j;
        if (i < N_NODES) g_rowptr[i] = local[j] + off;
    }

    __syncthreads();
    if (tid == 0) {
        int t = atomicAdd(&g_rowcnt[N_NODES + 1], 1);
        if (t == SCAN_GRID - 1) {
            g_rowcnt[N_NODES] = 0;
            g_rowcnt[N_NODES + 1] = 0;
            ((volatile int*)g_rowcnt)[N_NODES + 4] = 0;
        }
    }
}

// fill: pos = rowptr[dst] + rank; 8 edges per thread for MLP
__global__ void fill_kernel(const int* __restrict__ src,
                            const int* __restrict__ dst) {
    int e8 = (blockIdx.x * blockDim.x + threadIdx.x) * 8;
    if (e8 < E_EDGES) {
        int4 s0 = *reinterpret_cast<const int4*>(src + e8);
        int4 s1 = *reinterpret_cast<const int4*>(src + e8 + 4);
        int4 d0 = *reinterpret_cast<const int4*>(dst + e8);
        int4 d1 = *reinterpret_cast<const int4*>(dst + e8 + 4);
        int4 r0 = *reinterpret_cast<const int4*>(g_rank + e8);
        int4 r1 = *reinterpret_cast<const int4*>(g_rank + e8 + 4);
        int p0 = __ldg(&g_rowptr[d0.x]);
        int p1 = __ldg(&g_rowptr[d0.y]);
        int p2 = __ldg(&g_rowptr[d0.z]);
        int p3 = __ldg(&g_rowptr[d0.w]);
        int p4 = __ldg(&g_rowptr[d1.x]);
        int p5 = __ldg(&g_rowptr[d1.y]);
        int p6 = __ldg(&g_rowptr[d1.z]);
        int p7 = __ldg(&g_rowptr[d1.w]);
        g_csr_src[p0 + r0.x] = s0.x;
        g_csr_src[p1 + r0.y] = s0.y;
        g_csr_src[p2 + r0.z] = s0.z;
        g_csr_src[p3 + r0.w] = s0.w;
        g_csr_src[p4 + r1.x] = s1.x;
        g_csr_src[p5 + r1.y] = s1.y;
        g_csr_src[p6 + r1.z] = s1.z;
        g_csr_src[p7 + r1.w] = s1.w;
    }
}

// ---------------------------------------------------------------------------
// Gather layer 1 (fp32, 128 dims, warp per node) — 4x unrolled
// ---------------------------------------------------------------------------
__global__ void gather1_kernel(const float* __restrict__ x) {
    int node = (blockIdx.x * blockDim.x + threadIdx.x) >> 5;
    int lane = threadIdx.x & 31;
    if (node >= N_NODES) return;
    int beg = g_rowptr[node];
    int end = g_rowptr[node + 1];

    float4 acc = *reinterpret_cast<const float4*>(x + (size_t)node * D + lane * 4);

    for (int base = beg; base < end; base += 32) {
        int idx = 0;
        if (base + lane < end) idx = __ldg(&g_csr_src[base + lane]);
        int m = end - base; if (m > 32) m = 32;
        int j = 0;
        for (; j + 4 <= m; j += 4) {
            int s0 = __shfl_sync(0xffffffffu, idx, j);
            int s1 = __shfl_sync(0xffffffffu, idx, j + 1);
            int s2 = __shfl_sync(0xffffffffu, idx, j + 2);
            int s3 = __shfl_sync(0xffffffffu, idx, j + 3);
            float4 v0 = *reinterpret_cast<const float4*>(x + (size_t)s0 * D + lane * 4);
            float4 v1 = *reinterpret_cast<const float4*>(x + (size_t)s1 * D + lane * 4);
            float4 v2 = *reinterpret_cast<const float4*>(x + (size_t)s2 * D + lane * 4);
            float4 v3 = *reinterpret_cast<const float4*>(x + (size_t)s3 * D + lane * 4);
            acc.x += (v0.x + v1.x) + (v2.x + v3.x);
            acc.y += (v0.y + v1.y) + (v2.y + v3.y);
            acc.z += (v0.z + v1.z) + (v2.z + v3.z);
            acc.w += (v0.w + v1.w) + (v2.w + v3.w);
        }
        for (; j < m; j++) {
            int s = __shfl_sync(0xffffffffu, idx, j);
            float4 v = *reinterpret_cast<const float4*>(x + (size_t)s * D + lane * 4);
            acc.x += v.x; acc.y += v.y; acc.z += v.z; acc.w += v.w;
        }
    }
    float inv = 1.0f / (float)(end - beg + 1);
    acc.x *= inv; acc.y *= inv; acc.z *= inv; acc.w *= inv;
    *reinterpret_cast<float4*>(g_agg1 + (size_t)node * D + lane * 4) = acc;
}

// ---------------------------------------------------------------------------
// Fused two-layer GEMM via mma.sync bf16 (2-way split, 3 products).
// 512 threads, 128-row tile. W2 in its own smem region, loaded up front.
// smem: bias 512B + A hi/lo 69.6KB + Wc hi/lo 69.6KB + W2 hi/lo 17.4KB ~ 157KB
// ---------------------------------------------------------------------------
#define KW 64            // k-pairs per row
#define KWS 68           // padded word stride
#define TILE_W (128 * KWS)
#define W2TILE_W (DOUT * KWS)
#define FG_SMEM ((128 + 4 * TILE_W + 2 * W2TILE_W) * 4)

__global__ void __launch_bounds__(512, 1) fusedgemm_kernel() {
    extern __shared__ uint32_t smu[];
    float* bias     = (float*)smu;          // 128 floats
    uint32_t* sAh   = smu + 128;
    uint32_t* sAl   = sAh + TILE_W;
    uint32_t* sWh   = sAl + TILE_W;
    uint32_t* sWl   = sWh + TILE_W;
    uint32_t* sW2h  = sWl + TILE_W;
    uint32_t* sW2l  = sW2h + W2TILE_W;

    int tid = threadIdx.x;
    int w = tid >> 5, lane = tid & 31;
    int g = lane >> 2, qi = lane & 3;
    int row0 = blockIdx.x * 128;

    if (tid < D) bias[tid] = g_bc[tid];
    // A tile: load fp32, split+pack into sAh/sAl
    for (int i = tid; i < 128 * 32; i += 512) {
        int r = i >> 5, c4 = (i & 31) << 2;
        float4 v = make_float4(0.f, 0.f, 0.f, 0.f);
        int row = row0 + r;
        if (row < N_NODES) v = *reinterpret_cast<const float4*>(g_agg1 + (size_t)row * D + c4);
        uint32_t hw0, lw0, hw1, lw1;
        split_pack(v.x, v.y, hw0, lw0);
        split_pack(v.z, v.w, hw1, lw1);
        int o = r * KWS + (c4 >> 1);
        sAh[o] = hw0; sAh[o + 1] = hw1;
        sAl[o] = lw0; sAl[o + 1] = lw1;
    }
    // Wc packed images -> smem (stride 64 -> 68)
    for (int i = tid; i < 128 * 32; i += 512) {  // uint2 units
        int r = i >> 5, kw2 = (i & 31) << 1;
        uint2 h = *reinterpret_cast<const uint2*>(&g_WcP_h[r * KW + kw2]);
        uint2 l = *reinterpret_cast<const uint2*>(&g_WcP_l[r * KW + kw2]);
        *reinterpret_cast<uint2*>(&sWh[r * KWS + kw2]) = h;
        *reinterpret_cast<uint2*>(&sWl[r * KWS + kw2]) = l;
    }
    // W2 packed images -> dedicated smem region, loaded up front
    for (int i = tid; i < DOUT * 32; i += 512) {  // uint2 units
        int r = i >> 5, kw2 = (i & 31) << 1;
        uint2 h = *reinterpret_cast<const uint2*>(&g_W2P_h[r * KW + kw2]);
        uint2 l = *reinterpret_cast<const uint2*>(&g_W2P_l[r * KW + kw2]);
        *reinterpret_cast<uint2*>(&sW2h[r * KWS + kw2]) = h;
        *reinterpret_cast<uint2*>(&sW2l[r * KWS + kw2]) = l;
    }
    __syncthreads();

    // ---- layer 1: warp tile 32 rows x 32 cols, K=128 in 8 steps of 16 ----
    int rw0 = (w >> 2) * 32;
    int cw0 = (w & 3) * 32;
    float acc[2][4][4];
#pragma unroll
    for (int mt = 0; mt < 2; mt++)
#pragma unroll
        for (int nt = 0; nt < 4; nt++)
#pragma unroll
            for (int j = 0; j < 4; j++) acc[mt][nt][j] = 0.f;

#pragma unroll
    for (int ks = 0; ks < 8; ks++) {
        int kw0 = ks * 8;
        uint32_t ah[2][4], al[2][4];
#pragma unroll
        for (int mt = 0; mt < 2; mt++) {
            int rb = rw0 + mt * 16;
            ah[mt][0] = sAh[(rb + g) * KWS + kw0 + qi];
            ah[mt][1] = sAh[(rb + g + 8) * KWS + kw0 + qi];
            ah[mt][2] = sAh[(rb + g) * KWS + kw0 + qi + 4];
            ah[mt][3] = sAh[(rb + g + 8) * KWS + kw0 + qi + 4];
            al[mt][0] = sAl[(rb + g) * KWS + kw0 + qi];
            al[mt][1] = sAl[(rb + g + 8) * KWS + kw0 + qi];
            al[mt][2] = sAl[(rb + g) * KWS + kw0 + qi + 4];
            al[mt][3] = sAl[(rb + g + 8) * KWS + kw0 + qi + 4];
        }
#pragma unroll
        for (int nt = 0; nt < 4; nt++) {
            int nb = cw0 + nt * 8 + g;
            uint32_t bh0 = sWh[nb * KWS + kw0 + qi];
            uint32_t bh1 = sWh[nb * KWS + kw0 + qi + 4];
            uint32_t bl0 = sWl[nb * KWS + kw0 + qi];
            uint32_t bl1 = sWl[nb * KWS + kw0 + qi + 4];
#pragma unroll
            for (int mt = 0; mt < 2; mt++) {
                mma_bf16(acc[mt][nt], ah[mt], bh0, bh1);
                mma_bf16(acc[mt][nt], al[mt], bh0, bh1);
                mma_bf16(acc[mt][nt], ah[mt], bl0, bl1);
            }
        }
    }
    __syncthreads();

    // ---- epilogue 1: bias + relu, split-pack h1 back into sAh/sAl ----
#pragma unroll
    for (int mt = 0; mt < 2; mt++) {
        int rb = rw0 + mt * 16;
#pragma unroll
        for (int nt = 0; nt < 4; nt++) {
            int c0 = cw0 + nt * 8 + qi * 2;
            float b0 = bias[c0], b1 = bias[c0 + 1];
            int ow = (c0 >> 1);
            {
                float f0 = fmaxf(acc[mt][nt][0] + b0, 0.f);
                float f1 = fmaxf(acc[mt][nt][1] + b1, 0.f);
                uint32_t hw, lw;
                split_pack(f0, f1, hw, lw);
                sAh[(rb + g) * KWS + ow] = hw;
                sAl[(rb + g) * KWS + ow] = lw;
            }
            {
                float f0 = fmaxf(acc[mt][nt][2] + b0, 0.f);
                float f1 = fmaxf(acc[mt][nt][3] + b1, 0.f);
                uint32_t hw, lw;
                split_pack(f0, f1, hw, lw);
                sAh[(rb + g + 8) * KWS + ow] = hw;
                sAl[(rb + g + 8) * KWS + ow] = lw;
            }
        }
    }
    __syncthreads();

    // ---- layer 2: warp tile 32 rows x 16 cols (W2 already resident) ----
    int cw2 = (w & 3) * 16;
    float acc2[2][2][4];
#pragma unroll
    for (int mt = 0; mt < 2; mt++)
#pragma unroll
        for (int nt = 0; nt < 2; nt++)
#pragma unroll
            for (int j = 0; j < 4; j++) acc2[mt][nt][j] = 0.f;

#pragma unroll
    for (int ks = 0; ks < 8; ks++) {
        int kw0 = ks * 8;
        uint32_t ah[2][4], al[2][4];
#pragma unroll
        for (int mt = 0; mt < 2; mt++) {
            int rb = rw0 + mt * 16;
            ah[mt][0] = sAh[(rb + g) * KWS + kw0 + qi];
            ah[mt][1] = sAh[(rb + g + 8) * KWS + kw0 + qi];
            ah[mt][2] = sAh[(rb + g) * KWS + kw0 + qi + 4];
            ah[mt][3] = sAh[(rb + g + 8) * KWS + kw0 + qi + 4];
            al[mt][0] = sAl[(rb + g) * KWS + kw0 + qi];
            al[mt][1] = sAl[(rb + g + 8) * KWS + kw0 + qi];
            al[mt][2] = sAl[(rb + g) * KWS + kw0 + qi + 4];
            al[mt][3] = sAl[(rb + g + 8) * KWS + kw0 + qi + 4];
        }
#pragma unroll
        for (int nt = 0; nt < 2; nt++) {
            int nb = cw2 + nt * 8 + g;
            uint32_t bh0 = sW2h[nb * KWS + kw0 + qi];
            uint32_t bh1 = sW2h[nb * KWS + kw0 + qi + 4];
            uint32_t bl0 = sW2l[nb * KWS + kw0 + qi];
            uint32_t bl1 = sW2l[nb * KWS + kw0 + qi + 4];
#pragma unroll
            for (int mt = 0; mt < 2; mt++) {
                mma_bf16(acc2[mt][nt], ah[mt], bh0, bh1);
                mma_bf16(acc2[mt][nt], al[mt], bh0, bh1);
                mma_bf16(acc2[mt][nt], ah[mt], bl0, bl1);
            }
        }
    }
    __syncthreads();

    // ---- epilogue 2: stage h2 fp32 in smem (stride 66), coalesced store ----
    float* h2s = (float*)sAh;   // 128*66*4 = 33.8KB fits in sAh tile
#pragma unroll
    for (int mt = 0; mt < 2; mt++) {
        int rb = rw0 + mt * 16;
#pragma unroll
        for (int nt = 0; nt < 2; nt++) {
            int c0 = cw2 + nt * 8 + qi * 2;
            h2s[(rb + g) * 66 + c0]         = acc2[mt][nt][0];
            h2s[(rb + g) * 66 + c0 + 1]     = acc2[mt][nt][1];
            h2s[(rb + g + 8) * 66 + c0]     = acc2[mt][nt][2];
            h2s[(rb + g + 8) * 66 + c0 + 1] = acc2[mt][nt][3];
        }
    }
    __syncthreads();
    for (int i = tid; i < 128 * 32; i += 512) {
        int r = i >> 5, c2 = (i & 31) << 1;
        int row = row0 + r;
        if (row < N_NODES) {
            float2 v = *reinterpret_cast<const float2*>(&h2s[r * 66 + c2]);
            *reinterpret_cast<float2*>(&g_h2[(size_t)row * DOUT + c2]) = v;
        }
    }
}

// ---------------------------------------------------------------------------
// Gather layer 2 + bias + L2 normalize: HALF-WARP per node, float4 lanes
// ---------------------------------------------------------------------------
__global__ void gather2_kernel(const float* __restrict__ b2,
                               float* __restrict__ out) {
    int gw = (blockIdx.x * blockDim.x + threadIdx.x) >> 5;
    int lane = threadIdx.x & 31;
    int half = lane >> 4, l = lane & 15;
    int node = gw * 2 + half;
    if (node >= N_NODES) return;
    unsigned hmask = 0xFFFFu << (half * 16);
    int sbase = half * 16;

    int beg = g_rowptr[node];
    int end = g_rowptr[node + 1];

    float4 acc = *reinterpret_cast<const float4*>(g_h2 + (size_t)node * DOUT + l * 4);

    for (int base = beg; base < end; base += 16) {
        int idx = 0;
        if (base + l < end) idx = __ldg(&g_csr_src[base + l]);
        int m = end - base; if (m > 16) m = 16;
        int j = 0;
        for (; j + 4 <= m; j += 4) {
            int s0 = __shfl_sync(hmask, idx, sbase + j);
            int s1 = __shfl_sync(hmask, idx, sbase + j + 1);
            int s2 = __shfl_sync(hmask, idx, sbase + j + 2);
            int s3 = __shfl_sync(hmask, idx, sbase + j + 3);
            float4 v0 = *reinterpret_cast<const float4*>(g_h2 + (size_t)s0 * DOUT + l * 4);
            float4 v1 = *reinterpret_cast<const float4*>(g_h2 + (size_t)s1 * DOUT + l * 4);
            float4 v2 = *reinterpret_cast<const float4*>(g_h2 + (size_t)s2 * DOUT + l * 4);
            float4 v3 = *reinterpret_cast<const float4*>(g_h2 + (size_t)s3 * DOUT + l * 4);
            acc.x += (v0.x + v1.x) + (v2.x + v3.x);
            acc.y += (v0.y + v1.y) + (v2.y + v3.y);
            acc.z += (v0.z + v1.z) + (v2.z + v3.z);
            acc.w += (v0.w + v1.w) + (v2.w + v3.w);
        }
        for (; j < m; j++) {
            int s = __shfl_sync(hmask, idx, sbase + j);
            float4 v = *reinterpret_cast<const float4*>(g_h2 + (size_t)s * DOUT + l * 4);
            acc.x += v.x; acc.y += v.y; acc.z += v.z; acc.w += v.w;
        }
    }
    float inv = 1.0f / (float)(end - beg + 1);
    float4 b = *reinterpret_cast<const float4*>(b2 + l * 4);
    float a0 = acc.x * inv + b.x;
    float a1 = acc.y * inv + b.y;
    float a2 = acc.z * inv + b.z;
    float a3 = acc.w * inv + b.w;
    float ss = a0 * a0 + a1 * a1 + a2 * a2 + a3 * a3;
#pragma unroll
    for (int o = 8; o; o >>= 1) ss += __shfl_xor_sync(hmask, ss, o);
    float s = 1.0f / fmaxf(sqrtf(ss), 1e-12f);
    float4 o4 = make_float4(a0 * s, a1 * s, a2 * s, a3 * s);
    *reinterpret_cast<float4*>(&out[(size_t)node * DOUT + l * 4]) = o4;
}

// ---------------------------------------------------------------------------
extern "C" void kernel_launch(void* const* d_in, const int* in_sizes, int n_in,
                              void* d_out, int out_size) {
    const float* x     = (const float*)d_in[0];
    const int*   ei    = (const int*)d_in[1];
    const float* W_pre = (const float*)d_in[2];
    const float* b_pre = (const float*)d_in[3];
    const float* W1    = (const float*)d_in[4];
    const float* b1    = (const float*)d_in[5];
    const float* W2    = (const float*)d_in[6];
    const float* b2    = (const float*)d_in[7];
    float* out = (float*)d_out;

    const int* src = ei;
    const int* dst = ei + E_EDGES;

    static bool attr_set = false;
    if (!attr_set) {
        cudaFuncSetAttribute(fusedgemm_kernel,
                             cudaFuncAttributeMaxDynamicSharedMemorySize, FG_SMEM);
        attr_set = true;
    }

    prephist_kernel<<<PH_BLOCKS, 256>>>(dst, W_pre, b_pre, W1, b1, W2);
    scan_kernel<<<SCAN_GRID, 256>>>();
    fill_kernel<<<(E_EDGES / 8 + 255) / 256, 256>>>(src, dst);
    gather1_kernel<<<(N_NODES * 32 + 255) / 256, 256>>>(x);
    fusedgemm_kernel<<<(N_NODES + 127) / 128, 512, FG_SMEM>>>();
    gather2_kernel<<<((N_NODES + 1) / 2 * 32 + 255) / 256, 256>>>(b2, out);
}